// round 1
// baseline (speedup 1.0000x reference)
#include <cuda_runtime.h>
#include <math.h>

// ---------------------------------------------------------------------------
// Problem dims (fixed)
// ---------------------------------------------------------------------------
#define BATCH   32
#define SEQ     512
#define DMODEL  512
#define NHEADS  8
#define HDIM    64
#define DFF     2048
#define MTOK    (BATCH * SEQ)          // 16384 rows
#define LN_EPS  1e-12f

// ---------------------------------------------------------------------------
// Scratch (device globals; no runtime allocation allowed)
// ---------------------------------------------------------------------------
__device__ float g_q[MTOK * DMODEL];
__device__ float g_k[MTOK * DMODEL];
__device__ float g_v[MTOK * DMODEL];
__device__ float g_ctx[MTOK * DMODEL];
__device__ float g_t0[MTOK * DMODEL];      // generic [MTOK, DMODEL] temp
__device__ float g_attnln[MTOK * DMODEL];  // output of first LN
__device__ float g_ff[MTOK * DFF];         // FFN hidden

// ---------------------------------------------------------------------------
// Generic SGEMM: C[M,N] = A[M,K] @ B[K,N] + bias[N], optional exact GELU.
// Block tile 64x64, K-tile 16, 256 threads, 4x4 per-thread microtile.
// M, N, K all multiples of 64/16 here.
// ---------------------------------------------------------------------------
#define BM 64
#define BN 64
#define BKT 16

__global__ void gemm_bias_kernel(const float* __restrict__ A,
                                 const float* __restrict__ Bm,
                                 const float* __restrict__ bias,
                                 float* __restrict__ C,
                                 int M, int N, int K, int do_gelu)
{
    __shared__ float As[BKT][BM];   // As[k][m]
    __shared__ float Bs[BKT][BN];   // Bs[k][n]

    const int tid = threadIdx.x;
    const int row0 = blockIdx.y * BM;
    const int col0 = blockIdx.x * BN;

    const int tx = tid & 15;        // 16 col groups
    const int ty = tid >> 4;        // 16 row groups

    // A loader: 64 rows x 16 k, 4 threads per row, float4 each
    const int ar = tid >> 2;
    const int ak = (tid & 3) * 4;
    // B loader: 16 rows x 64 cols, 16 threads per row, float4 each
    const int bkr = tid >> 4;
    const int bc  = (tid & 15) * 4;

    float acc[4][4] = {};

    for (int k0 = 0; k0 < K; k0 += BKT) {
        float4 av = *(const float4*)(A + (size_t)(row0 + ar) * K + k0 + ak);
        As[ak + 0][ar] = av.x;
        As[ak + 1][ar] = av.y;
        As[ak + 2][ar] = av.z;
        As[ak + 3][ar] = av.w;
        float4 bv = *(const float4*)(Bm + (size_t)(k0 + bkr) * N + col0 + bc);
        *(float4*)&Bs[bkr][bc] = bv;
        __syncthreads();

#pragma unroll
        for (int kk = 0; kk < BKT; kk++) {
            float4 a4 = *(const float4*)&As[kk][ty * 4];
            float4 b4 = *(const float4*)&Bs[kk][tx * 4];
            float a[4] = {a4.x, a4.y, a4.z, a4.w};
            float b[4] = {b4.x, b4.y, b4.z, b4.w};
#pragma unroll
            for (int i = 0; i < 4; i++)
#pragma unroll
                for (int j = 0; j < 4; j++)
                    acc[i][j] = fmaf(a[i], b[j], acc[i][j]);
        }
        __syncthreads();
    }

    // epilogue
    const int cb = col0 + tx * 4;
    float bb[4] = {bias[cb], bias[cb + 1], bias[cb + 2], bias[cb + 3]};
#pragma unroll
    for (int i = 0; i < 4; i++) {
        float4 out;
        float v[4];
#pragma unroll
        for (int j = 0; j < 4; j++) {
            float c = acc[i][j] + bb[j];
            if (do_gelu)
                c = 0.5f * c * (1.0f + erff(c * 0.70710678118654752f));
            v[j] = c;
        }
        out.x = v[0]; out.y = v[1]; out.z = v[2]; out.w = v[3];
        *(float4*)(C + (size_t)(row0 + ty * 4 + i) * N + cb) = out;
    }
}

// ---------------------------------------------------------------------------
// Fused attention: one block per (query-tile of 64, head, batch).
// smem: Qs transposed [d][q] pitch 65, K transposed / V natural buffer,
//       full score block [64][512].
// ---------------------------------------------------------------------------
#define ATTN_SMEM_FLOATS (65 * 64 * 2 + 64 * 512)
#define ATTN_SMEM_BYTES  (ATTN_SMEM_FLOATS * 4)

__global__ void attn_kernel(const float* __restrict__ Qg,
                            const float* __restrict__ Kg,
                            const float* __restrict__ Vg,
                            const float* __restrict__ mask,
                            float* __restrict__ Og)
{
    extern __shared__ float sm[];
    float* Qs = sm;                 // [64 d][65]  Qs[d*65 + r]
    float* KVs = sm + 65 * 64;      // K: [d*65 + kr]; V: [k*64 + d]
    float* Ss = sm + 2 * 65 * 64;   // [64 q][512 k]

    const int tid = threadIdx.x;
    const int qb = blockIdx.x;
    const int h  = blockIdx.y;
    const int b  = blockIdx.z;
    const int q0 = qb * 64;
    const float scale = 0.125f;     // 1/sqrt(64)

    const size_t base = ((size_t)b * SEQ) * DMODEL + (size_t)h * HDIM;
    const float* mrow = mask + (size_t)b * SEQ * SEQ;

    // load Q tile transposed
#pragma unroll
    for (int i = 0; i < 16; i++) {
        int e = tid + i * 256;
        int r = e >> 6, d = e & 63;
        Qs[d * 65 + r] = Qg[base + (size_t)(q0 + r) * DMODEL + d];
    }

    const int tx = tid & 15;
    const int ty = tid >> 4;

    // ---- phase 1: scores = scale * Q K^T + mask ----
    for (int kb = 0; kb < 8; kb++) {
        const int k0 = kb * 64;
        __syncthreads();
#pragma unroll
        for (int i = 0; i < 16; i++) {
            int e = tid + i * 256;
            int r = e >> 6, d = e & 63;
            KVs[d * 65 + r] = Kg[base + (size_t)(k0 + r) * DMODEL + d];
        }
        __syncthreads();

        float acc[4][4] = {};
#pragma unroll 4
        for (int kk = 0; kk < 64; kk++) {
            float a[4], bv[4];
#pragma unroll
            for (int i = 0; i < 4; i++) {
                a[i]  = Qs[kk * 65 + ty * 4 + i];
                bv[i] = KVs[kk * 65 + tx * 4 + i];
            }
#pragma unroll
            for (int i = 0; i < 4; i++)
#pragma unroll
                for (int j = 0; j < 4; j++)
                    acc[i][j] = fmaf(a[i], bv[j], acc[i][j]);
        }
#pragma unroll
        for (int i = 0; i < 4; i++) {
            int qr = ty * 4 + i;
#pragma unroll
            for (int j = 0; j < 4; j++) {
                int kc = k0 + tx * 4 + j;
                Ss[qr * 512 + kc] =
                    acc[i][j] * scale + mrow[(size_t)(q0 + qr) * SEQ + kc];
            }
        }
    }
    __syncthreads();

    // ---- phase 2: softmax, warp per 8 consecutive rows ----
    {
        const int warp = tid >> 5;
        const int lane = tid & 31;
        for (int rr = 0; rr < 8; rr++) {
            float* row = Ss + (warp * 8 + rr) * 512;
            float m = -1e30f;
            for (int j = lane; j < 512; j += 32) m = fmaxf(m, row[j]);
#pragma unroll
            for (int off = 16; off; off >>= 1)
                m = fmaxf(m, __shfl_xor_sync(0xffffffffu, m, off));
            float s = 0.f;
            for (int j = lane; j < 512; j += 32) {
                float e = expf(row[j] - m);
                row[j] = e;
                s += e;
            }
#pragma unroll
            for (int off = 16; off; off >>= 1)
                s += __shfl_xor_sync(0xffffffffu, s, off);
            float inv = 1.0f / s;
            for (int j = lane; j < 512; j += 32) row[j] *= inv;
        }
    }

    // ---- phase 3: O = P @ V ----
    float acc[4][4] = {};
    for (int kb = 0; kb < 8; kb++) {
        const int k0 = kb * 64;
        __syncthreads();
#pragma unroll
        for (int i = 0; i < 16; i++) {
            int e = tid + i * 256;
            int r = e >> 6, d = e & 63;
            KVs[r * 64 + d] = Vg[base + (size_t)(k0 + r) * DMODEL + d];
        }
        __syncthreads();

#pragma unroll 4
        for (int kk = 0; kk < 64; kk++) {
            float4 b4 = *(const float4*)&KVs[kk * 64 + tx * 4];
            float bv[4] = {b4.x, b4.y, b4.z, b4.w};
            float a[4];
#pragma unroll
            for (int i = 0; i < 4; i++)
                a[i] = Ss[(ty * 4 + i) * 512 + k0 + kk];
#pragma unroll
            for (int i = 0; i < 4; i++)
#pragma unroll
                for (int j = 0; j < 4; j++)
                    acc[i][j] = fmaf(a[i], bv[j], acc[i][j]);
        }
    }

#pragma unroll
    for (int i = 0; i < 4; i++) {
        float4 out;
        out.x = acc[i][0]; out.y = acc[i][1]; out.z = acc[i][2]; out.w = acc[i][3];
        *(float4*)(Og + base + (size_t)(q0 + ty * 4 + i) * DMODEL + tx * 4) = out;
    }
}

// ---------------------------------------------------------------------------
// LayerNorm with residual: out = LN(y + res) * g + b   (row length 512)
// ---------------------------------------------------------------------------
__global__ void ln_residual_kernel(const float* __restrict__ y,
                                   const float* __restrict__ res,
                                   const float* __restrict__ g,
                                   const float* __restrict__ bta,
                                   float* __restrict__ out)
{
    __shared__ float red[256];
    const int r = blockIdx.x;
    const int tid = threadIdx.x;
    const size_t off = (size_t)r * DMODEL;

    float v0 = y[off + tid]        + res[off + tid];
    float v1 = y[off + tid + 256]  + res[off + tid + 256];

    red[tid] = v0 + v1;
    __syncthreads();
#pragma unroll
    for (int s = 128; s; s >>= 1) {
        if (tid < s) red[tid] += red[tid + s];
        __syncthreads();
    }
    float mean = red[0] * (1.0f / 512.0f);
    __syncthreads();

    float d0 = v0 - mean, d1 = v1 - mean;
    red[tid] = d0 * d0 + d1 * d1;
    __syncthreads();
#pragma unroll
    for (int s = 128; s; s >>= 1) {
        if (tid < s) red[tid] += red[tid + s];
        __syncthreads();
    }
    float inv = rsqrtf(red[0] * (1.0f / 512.0f) + LN_EPS);

    out[off + tid]       = d0 * inv * g[tid]       + bta[tid];
    out[off + tid + 256] = d1 * inv * g[tid + 256] + bta[tid + 256];
}

// ---------------------------------------------------------------------------
// launch
// ---------------------------------------------------------------------------
extern "C" void kernel_launch(void* const* d_in, const int* in_sizes, int n_in,
                              void* d_out, int out_size)
{
    const float* x     = (const float*)d_in[0];
    const float* mask  = (const float*)d_in[1];
    const float* Wq    = (const float*)d_in[2];
    const float* bq    = (const float*)d_in[3];
    const float* Wk    = (const float*)d_in[4];
    const float* bk    = (const float*)d_in[5];
    const float* Wv    = (const float*)d_in[6];
    const float* bv    = (const float*)d_in[7];
    const float* Wo    = (const float*)d_in[8];
    const float* bo    = (const float*)d_in[9];
    const float* ln1g  = (const float*)d_in[10];
    const float* ln1b  = (const float*)d_in[11];
    const float* W1    = (const float*)d_in[12];
    const float* b1    = (const float*)d_in[13];
    const float* W2    = (const float*)d_in[14];
    const float* b2    = (const float*)d_in[15];
    const float* ln2g  = (const float*)d_in[16];
    const float* ln2b  = (const float*)d_in[17];
    float* out = (float*)d_out;

    float *q, *k, *v, *ctx, *t0, *aln, *ff;
    cudaGetSymbolAddress((void**)&q,   g_q);
    cudaGetSymbolAddress((void**)&k,   g_k);
    cudaGetSymbolAddress((void**)&v,   g_v);
    cudaGetSymbolAddress((void**)&ctx, g_ctx);
    cudaGetSymbolAddress((void**)&t0,  g_t0);
    cudaGetSymbolAddress((void**)&aln, g_attnln);
    cudaGetSymbolAddress((void**)&ff,  g_ff);

    cudaFuncSetAttribute(attn_kernel,
                         cudaFuncAttributeMaxDynamicSharedMemorySize,
                         ATTN_SMEM_BYTES);

    dim3 blk(256);

    // QKV projections
    {
        dim3 grid(DMODEL / BN, MTOK / BM);
        gemm_bias_kernel<<<grid, blk>>>(x, Wq, bq, q, MTOK, DMODEL, DMODEL, 0);
        gemm_bias_kernel<<<grid, blk>>>(x, Wk, bk, k, MTOK, DMODEL, DMODEL, 0);
        gemm_bias_kernel<<<grid, blk>>>(x, Wv, bv, v, MTOK, DMODEL, DMODEL, 0);
    }

    // attention
    {
        dim3 grid(SEQ / 64, NHEADS, BATCH);
        attn_kernel<<<grid, blk, ATTN_SMEM_BYTES>>>(q, k, v, mask, ctx);
    }

    // output projection + residual LN
    {
        dim3 grid(DMODEL / BN, MTOK / BM);
        gemm_bias_kernel<<<grid, blk>>>(ctx, Wo, bo, t0, MTOK, DMODEL, DMODEL, 0);
        ln_residual_kernel<<<MTOK, 256>>>(t0, x, ln1g, ln1b, aln);
    }

    // FFN
    {
        dim3 grid1(DFF / BN, MTOK / BM);
        gemm_bias_kernel<<<grid1, blk>>>(aln, W1, b1, ff, MTOK, DFF, DMODEL, 1);
        dim3 grid2(DMODEL / BN, MTOK / BM);
        gemm_bias_kernel<<<grid2, blk>>>(ff, W2, b2, t0, MTOK, DMODEL, DFF, 0);
        ln_residual_kernel<<<MTOK, 256>>>(t0, aln, ln2g, ln2b, out);
    }
}

// round 3
// speedup vs baseline: 1.7803x; 1.7803x over previous
#include <cuda_runtime.h>
#include <cuda_bf16.h>
#include <math.h>
#include <stdint.h>

// ---------------------------------------------------------------------------
// Problem dims (fixed)
// ---------------------------------------------------------------------------
#define BATCH   32
#define SEQ     512
#define DMODEL  512
#define NHEADS  8
#define HDIM    64
#define DFF     2048
#define MTOK    (BATCH * SEQ)          // 16384 rows
#define LN_EPS  1e-12f

// ---------------------------------------------------------------------------
// Scratch (device globals; no runtime allocation allowed)
// ---------------------------------------------------------------------------
__device__ float g_q[MTOK * DMODEL];
__device__ float g_k[MTOK * DMODEL];
__device__ float g_v[MTOK * DMODEL];
__device__ float g_ctx[MTOK * DMODEL];
__device__ float g_t0[MTOK * DMODEL];
__device__ float g_attnln[MTOK * DMODEL];
__device__ float g_ff[MTOK * DFF];

// bf16 hi/lo split activations
__device__ __nv_bfloat16 g_xhi[MTOK * DMODEL];
__device__ __nv_bfloat16 g_xlo[MTOK * DMODEL];
__device__ __nv_bfloat16 g_chi[MTOK * DMODEL];
__device__ __nv_bfloat16 g_clo[MTOK * DMODEL];
__device__ __nv_bfloat16 g_ahi[MTOK * DMODEL];
__device__ __nv_bfloat16 g_alo[MTOK * DMODEL];
__device__ __nv_bfloat16 g_fhi[MTOK * DFF];
__device__ __nv_bfloat16 g_flo[MTOK * DFF];

// bf16 hi/lo split transposed weights [N][K]
__device__ __nv_bfloat16 g_wqhi[DMODEL * DMODEL];
__device__ __nv_bfloat16 g_wqlo[DMODEL * DMODEL];
__device__ __nv_bfloat16 g_wkhi[DMODEL * DMODEL];
__device__ __nv_bfloat16 g_wklo[DMODEL * DMODEL];
__device__ __nv_bfloat16 g_wvhi[DMODEL * DMODEL];
__device__ __nv_bfloat16 g_wvlo[DMODEL * DMODEL];
__device__ __nv_bfloat16 g_wohi[DMODEL * DMODEL];
__device__ __nv_bfloat16 g_wolo[DMODEL * DMODEL];
__device__ __nv_bfloat16 g_w1hi[DFF * DMODEL];
__device__ __nv_bfloat16 g_w1lo[DFF * DMODEL];
__device__ __nv_bfloat16 g_w2hi[DMODEL * DFF];
__device__ __nv_bfloat16 g_w2lo[DMODEL * DFF];

// ---------------------------------------------------------------------------
// mma.sync helper (bf16 -> f32, m16n8k16; supported on plain sm_103 target)
// ---------------------------------------------------------------------------
__device__ __forceinline__ void mma16816(float* c, const uint32_t* a, const uint32_t* b)
{
    asm volatile(
        "mma.sync.aligned.m16n8k16.row.col.f32.bf16.bf16.f32 "
        "{%0,%1,%2,%3}, {%4,%5,%6,%7}, {%8,%9}, {%0,%1,%2,%3};"
        : "+f"(c[0]), "+f"(c[1]), "+f"(c[2]), "+f"(c[3])
        : "r"(a[0]), "r"(a[1]), "r"(a[2]), "r"(a[3]), "r"(b[0]), "r"(b[1]));
}

// ---------------------------------------------------------------------------
// fp32 -> bf16 hi/lo split (elementwise, vectorized)
// ---------------------------------------------------------------------------
__device__ __forceinline__ void split1(float v, unsigned short& h, unsigned short& l) {
    __nv_bfloat16 hb = __float2bfloat16_rn(v);
    float r = v - __bfloat162float(hb);
    __nv_bfloat16 lb = __float2bfloat16_rn(r);
    h = __bfloat16_as_ushort(hb);
    l = __bfloat16_as_ushort(lb);
}

__global__ void split_kernel(const float* __restrict__ X,
                             __nv_bfloat16* __restrict__ hi,
                             __nv_bfloat16* __restrict__ lo, int n4)
{
    int i = blockIdx.x * blockDim.x + threadIdx.x;
    if (i >= n4) return;
    float4 x = ((const float4*)X)[i];
    unsigned short h0, h1, h2, h3, l0, l1, l2, l3;
    split1(x.x, h0, l0); split1(x.y, h1, l1);
    split1(x.z, h2, l2); split1(x.w, h3, l3);
    uint2 hv, lv;
    hv.x = (uint32_t)h0 | ((uint32_t)h1 << 16);
    hv.y = (uint32_t)h2 | ((uint32_t)h3 << 16);
    lv.x = (uint32_t)l0 | ((uint32_t)l1 << 16);
    lv.y = (uint32_t)l2 | ((uint32_t)l3 << 16);
    ((uint2*)hi)[i] = hv;
    ((uint2*)lo)[i] = lv;
}

// Transpose + split: W[K][N] fp32 -> hi/lo [N][K] bf16
__global__ void tsplit_kernel(const float* __restrict__ W,
                              __nv_bfloat16* __restrict__ hi,
                              __nv_bfloat16* __restrict__ lo,
                              int K, int N)
{
    __shared__ float tile[32][33];
    const int n0 = blockIdx.x * 32, k0 = blockIdx.y * 32;
    const int tx = threadIdx.x, ty = threadIdx.y;   // 32 x 8
#pragma unroll
    for (int i = 0; i < 32; i += 8)
        tile[ty + i][tx] = W[(size_t)(k0 + ty + i) * N + n0 + tx];
    __syncthreads();
#pragma unroll
    for (int i = 0; i < 32; i += 8) {
        float v = tile[tx][ty + i];
        unsigned short h, l;
        split1(v, h, l);
        size_t o = (size_t)(n0 + ty + i) * K + k0 + tx;
        hi[o] = __ushort_as_bfloat16(h);
        lo[o] = __ushort_as_bfloat16(l);
    }
}

// ---------------------------------------------------------------------------
// Tensor-core split-GEMM via mma.sync:
//   C[M,N] = (Ahi+Alo)[M,K] @ (Bhi+Blo)^T + bias, optional exact GELU
//   A row-major [M,K], B row-major [N,K] (k-contiguous = "col" operand).
//   CTA tile 128x64, k-tile 64, 8 warps (4 m x 2 n), warp tile 32x32.
//   D = Ahi*Bhi + Alo*Bhi + Ahi*Blo   (fp32 accum)
// ---------------------------------------------------------------------------
#define SA 72                      // padded smem stride (bf16 elems)
#define GM_A_ELEMS (128 * SA)      // 9216
#define GM_B_ELEMS (64 * SA)       // 4608
#define GM_SMEM_ELEMS (2 * GM_A_ELEMS + 2 * GM_B_ELEMS)   // 27648
#define GM_SMEM_BYTES (GM_SMEM_ELEMS * 2)                  // 55296

__global__ __launch_bounds__(256)
void gemm_mma(const __nv_bfloat16* __restrict__ Ahi,
              const __nv_bfloat16* __restrict__ Alo,
              const __nv_bfloat16* __restrict__ Bhi,
              const __nv_bfloat16* __restrict__ Blo,
              const float* __restrict__ bias,
              float* __restrict__ C,
              int M, int N, int K, int do_gelu)
{
    extern __shared__ __nv_bfloat16 smb[];
    __nv_bfloat16* As_hi = smb;
    __nv_bfloat16* As_lo = smb + GM_A_ELEMS;
    __nv_bfloat16* Bs_hi = smb + 2 * GM_A_ELEMS;
    __nv_bfloat16* Bs_lo = smb + 2 * GM_A_ELEMS + GM_B_ELEMS;

    const int tid = threadIdx.x;
    const int wid = tid >> 5;
    const int lid = tid & 31;
    const int gID = lid >> 2;        // 0..7
    const int t4  = lid & 3;         // 0..3

    const int row0 = blockIdx.y * 128;
    const int col0 = blockIdx.x * 64;
    const int m_off = (wid & 3) * 32;    // warp rows within CTA
    const int n_off = (wid >> 2) * 32;   // warp cols within CTA

    float acc[2][4][4];
#pragma unroll
    for (int mi = 0; mi < 2; mi++)
#pragma unroll
        for (int ni = 0; ni < 4; ni++)
#pragma unroll
            for (int j = 0; j < 4; j++) acc[mi][ni][j] = 0.f;

    const int nT = K >> 6;
    for (int t = 0; t < nT; t++) {
        const int kb = t << 6;

        // load A tile 128x64 (hi+lo), uint4 chunks of 8 bf16
#pragma unroll
        for (int i = 0; i < 4; i++) {
            int e = tid + i * 256;
            int r = e >> 3, g = e & 7;
            int ds = r * SA + g * 8;
            size_t src = (size_t)(row0 + r) * K + kb + g * 8;
            *(uint4*)&As_hi[ds] = *(const uint4*)&Ahi[src];
            *(uint4*)&As_lo[ds] = *(const uint4*)&Alo[src];
        }
        // load B tile 64x64 (hi+lo)
#pragma unroll
        for (int i = 0; i < 2; i++) {
            int e = tid + i * 256;
            int r = e >> 3, g = e & 7;
            int ds = r * SA + g * 8;
            size_t src = (size_t)(col0 + r) * K + kb + g * 8;
            *(uint4*)&Bs_hi[ds] = *(const uint4*)&Bhi[src];
            *(uint4*)&Bs_lo[ds] = *(const uint4*)&Blo[src];
        }
        __syncthreads();

#pragma unroll
        for (int kk = 0; kk < 64; kk += 16) {
            uint32_t ahi[2][4], alo[2][4], bhi[4][2], blo[4][2];
#pragma unroll
            for (int mi = 0; mi < 2; mi++) {
                int r = m_off + mi * 16 + gID;
                int base0 = r * SA + kk + t4 * 2;
                int base1 = (r + 8) * SA + kk + t4 * 2;
                ahi[mi][0] = *(const uint32_t*)&As_hi[base0];
                ahi[mi][1] = *(const uint32_t*)&As_hi[base1];
                ahi[mi][2] = *(const uint32_t*)&As_hi[base0 + 8];
                ahi[mi][3] = *(const uint32_t*)&As_hi[base1 + 8];
                alo[mi][0] = *(const uint32_t*)&As_lo[base0];
                alo[mi][1] = *(const uint32_t*)&As_lo[base1];
                alo[mi][2] = *(const uint32_t*)&As_lo[base0 + 8];
                alo[mi][3] = *(const uint32_t*)&As_lo[base1 + 8];
            }
#pragma unroll
            for (int ni = 0; ni < 4; ni++) {
                int n = n_off + ni * 8 + gID;
                int base = n * SA + kk + t4 * 2;
                bhi[ni][0] = *(const uint32_t*)&Bs_hi[base];
                bhi[ni][1] = *(const uint32_t*)&Bs_hi[base + 8];
                blo[ni][0] = *(const uint32_t*)&Bs_lo[base];
                blo[ni][1] = *(const uint32_t*)&Bs_lo[base + 8];
            }
#pragma unroll
            for (int mi = 0; mi < 2; mi++)
#pragma unroll
                for (int ni = 0; ni < 4; ni++) {
                    mma16816(acc[mi][ni], ahi[mi], bhi[ni]);
                    mma16816(acc[mi][ni], alo[mi], bhi[ni]);
                    mma16816(acc[mi][ni], ahi[mi], blo[ni]);
                }
        }
        __syncthreads();
    }

    // epilogue: bias + optional GELU, direct float2 stores
#pragma unroll
    for (int mi = 0; mi < 2; mi++) {
#pragma unroll
        for (int ni = 0; ni < 4; ni++) {
            int col = col0 + n_off + ni * 8 + t4 * 2;
            float b0 = bias[col], b1 = bias[col + 1];
#pragma unroll
            for (int half = 0; half < 2; half++) {
                int row = row0 + m_off + mi * 16 + gID + half * 8;
                float v0 = acc[mi][ni][half * 2 + 0] + b0;
                float v1 = acc[mi][ni][half * 2 + 1] + b1;
                if (do_gelu) {
                    v0 = 0.5f * v0 * (1.0f + erff(v0 * 0.70710678118654752f));
                    v1 = 0.5f * v1 * (1.0f + erff(v1 * 0.70710678118654752f));
                }
                float2 o; o.x = v0; o.y = v1;
                *(float2*)(C + (size_t)row * N + col) = o;
            }
        }
    }
}

// ---------------------------------------------------------------------------
// Fused attention (unchanged — proven correct)
// ---------------------------------------------------------------------------
#define ATTN_SMEM_FLOATS (65 * 64 * 2 + 64 * 512)
#define ATTN_SMEM_BYTES  (ATTN_SMEM_FLOATS * 4)

__global__ void attn_kernel(const float* __restrict__ Qg,
                            const float* __restrict__ Kg,
                            const float* __restrict__ Vg,
                            const float* __restrict__ mask,
                            float* __restrict__ Og)
{
    extern __shared__ float smf[];
    float* Qs = smf;
    float* KVs = smf + 65 * 64;
    float* Ss = smf + 2 * 65 * 64;

    const int tid = threadIdx.x;
    const int qb = blockIdx.x;
    const int h  = blockIdx.y;
    const int b  = blockIdx.z;
    const int q0 = qb * 64;
    const float scale = 0.125f;

    const size_t base = ((size_t)b * SEQ) * DMODEL + (size_t)h * HDIM;
    const float* mrow = mask + (size_t)b * SEQ * SEQ;

#pragma unroll
    for (int i = 0; i < 16; i++) {
        int e = tid + i * 256;
        int r = e >> 6, d = e & 63;
        Qs[d * 65 + r] = Qg[base + (size_t)(q0 + r) * DMODEL + d];
    }

    const int tx = tid & 15;
    const int ty = tid >> 4;

    for (int kb = 0; kb < 8; kb++) {
        const int k0 = kb * 64;
        __syncthreads();
#pragma unroll
        for (int i = 0; i < 16; i++) {
            int e = tid + i * 256;
            int r = e >> 6, d = e & 63;
            KVs[d * 65 + r] = Kg[base + (size_t)(k0 + r) * DMODEL + d];
        }
        __syncthreads();

        float acc[4][4] = {};
#pragma unroll 4
        for (int kk = 0; kk < 64; kk++) {
            float a[4], bv[4];
#pragma unroll
            for (int i = 0; i < 4; i++) {
                a[i]  = Qs[kk * 65 + ty * 4 + i];
                bv[i] = KVs[kk * 65 + tx * 4 + i];
            }
#pragma unroll
            for (int i = 0; i < 4; i++)
#pragma unroll
                for (int j = 0; j < 4; j++)
                    acc[i][j] = fmaf(a[i], bv[j], acc[i][j]);
        }
#pragma unroll
        for (int i = 0; i < 4; i++) {
            int qr = ty * 4 + i;
#pragma unroll
            for (int j = 0; j < 4; j++) {
                int kc = k0 + tx * 4 + j;
                Ss[qr * 512 + kc] =
                    acc[i][j] * scale + mrow[(size_t)(q0 + qr) * SEQ + kc];
            }
        }
    }
    __syncthreads();

    {
        const int warp = tid >> 5;
        const int lane = tid & 31;
        for (int rr = 0; rr < 8; rr++) {
            float* row = Ss + (warp * 8 + rr) * 512;
            float m = -1e30f;
            for (int j = lane; j < 512; j += 32) m = fmaxf(m, row[j]);
#pragma unroll
            for (int off = 16; off; off >>= 1)
                m = fmaxf(m, __shfl_xor_sync(0xffffffffu, m, off));
            float s = 0.f;
            for (int j = lane; j < 512; j += 32) {
                float e = expf(row[j] - m);
                row[j] = e;
                s += e;
            }
#pragma unroll
            for (int off = 16; off; off >>= 1)
                s += __shfl_xor_sync(0xffffffffu, s, off);
            float inv = 1.0f / s;
            for (int j = lane; j < 512; j += 32) row[j] *= inv;
        }
    }

    float acc[4][4] = {};
    for (int kb = 0; kb < 8; kb++) {
        const int k0 = kb * 64;
        __syncthreads();
#pragma unroll
        for (int i = 0; i < 16; i++) {
            int e = tid + i * 256;
            int r = e >> 6, d = e & 63;
            KVs[r * 64 + d] = Vg[base + (size_t)(k0 + r) * DMODEL + d];
        }
        __syncthreads();

#pragma unroll 4
        for (int kk = 0; kk < 64; kk++) {
            float4 b4 = *(const float4*)&KVs[kk * 64 + tx * 4];
            float bv[4] = {b4.x, b4.y, b4.z, b4.w};
            float a[4];
#pragma unroll
            for (int i = 0; i < 4; i++)
                a[i] = Ss[(ty * 4 + i) * 512 + k0 + kk];
#pragma unroll
            for (int i = 0; i < 4; i++)
#pragma unroll
                for (int j = 0; j < 4; j++)
                    acc[i][j] = fmaf(a[i], bv[j], acc[i][j]);
        }
    }

#pragma unroll
    for (int i = 0; i < 4; i++) {
        float4 out;
        out.x = acc[i][0]; out.y = acc[i][1]; out.z = acc[i][2]; out.w = acc[i][3];
        *(float4*)(Og + base + (size_t)(q0 + ty * 4 + i) * DMODEL + tx * 4) = out;
    }
}

// ---------------------------------------------------------------------------
// LayerNorm with residual (unchanged)
// ---------------------------------------------------------------------------
__global__ void ln_residual_kernel(const float* __restrict__ y,
                                   const float* __restrict__ res,
                                   const float* __restrict__ g,
                                   const float* __restrict__ bta,
                                   float* __restrict__ out)
{
    __shared__ float red[256];
    const int r = blockIdx.x;
    const int tid = threadIdx.x;
    const size_t off = (size_t)r * DMODEL;

    float v0 = y[off + tid]        + res[off + tid];
    float v1 = y[off + tid + 256]  + res[off + tid + 256];

    red[tid] = v0 + v1;
    __syncthreads();
#pragma unroll
    for (int s = 128; s; s >>= 1) {
        if (tid < s) red[tid] += red[tid + s];
        __syncthreads();
    }
    float mean = red[0] * (1.0f / 512.0f);
    __syncthreads();

    float d0 = v0 - mean, d1 = v1 - mean;
    red[tid] = d0 * d0 + d1 * d1;
    __syncthreads();
#pragma unroll
    for (int s = 128; s; s >>= 1) {
        if (tid < s) red[tid] += red[tid + s];
        __syncthreads();
    }
    float inv = rsqrtf(red[0] * (1.0f / 512.0f) + LN_EPS);

    out[off + tid]       = d0 * inv * g[tid]       + bta[tid];
    out[off + tid + 256] = d1 * inv * g[tid + 256] + bta[tid + 256];
}

// ---------------------------------------------------------------------------
// launch
// ---------------------------------------------------------------------------
extern "C" void kernel_launch(void* const* d_in, const int* in_sizes, int n_in,
                              void* d_out, int out_size)
{
    const float* x     = (const float*)d_in[0];
    const float* mask  = (const float*)d_in[1];
    const float* Wq    = (const float*)d_in[2];
    const float* bq    = (const float*)d_in[3];
    const float* Wk    = (const float*)d_in[4];
    const float* bk    = (const float*)d_in[5];
    const float* Wv    = (const float*)d_in[6];
    const float* bv    = (const float*)d_in[7];
    const float* Wo    = (const float*)d_in[8];
    const float* bo    = (const float*)d_in[9];
    const float* ln1g  = (const float*)d_in[10];
    const float* ln1b  = (const float*)d_in[11];
    const float* W1    = (const float*)d_in[12];
    const float* b1    = (const float*)d_in[13];
    const float* W2    = (const float*)d_in[14];
    const float* b2    = (const float*)d_in[15];
    const float* ln2g  = (const float*)d_in[16];
    const float* ln2b  = (const float*)d_in[17];
    float* out = (float*)d_out;

    float *q, *k, *v, *ctx, *t0, *aln, *ff;
    cudaGetSymbolAddress((void**)&q,   g_q);
    cudaGetSymbolAddress((void**)&k,   g_k);
    cudaGetSymbolAddress((void**)&v,   g_v);
    cudaGetSymbolAddress((void**)&ctx, g_ctx);
    cudaGetSymbolAddress((void**)&t0,  g_t0);
    cudaGetSymbolAddress((void**)&aln, g_attnln);
    cudaGetSymbolAddress((void**)&ff,  g_ff);

    __nv_bfloat16 *xhi, *xlo, *chi, *clo, *ahi, *alo, *fhi, *flo;
    cudaGetSymbolAddress((void**)&xhi, g_xhi);
    cudaGetSymbolAddress((void**)&xlo, g_xlo);
    cudaGetSymbolAddress((void**)&chi, g_chi);
    cudaGetSymbolAddress((void**)&clo, g_clo);
    cudaGetSymbolAddress((void**)&ahi, g_ahi);
    cudaGetSymbolAddress((void**)&alo, g_alo);
    cudaGetSymbolAddress((void**)&fhi, g_fhi);
    cudaGetSymbolAddress((void**)&flo, g_flo);

    __nv_bfloat16 *wqh, *wql, *wkh, *wkl, *wvh, *wvl, *woh, *wol, *w1h, *w1l, *w2h, *w2l;
    cudaGetSymbolAddress((void**)&wqh, g_wqhi);
    cudaGetSymbolAddress((void**)&wql, g_wqlo);
    cudaGetSymbolAddress((void**)&wkh, g_wkhi);
    cudaGetSymbolAddress((void**)&wkl, g_wklo);
    cudaGetSymbolAddress((void**)&wvh, g_wvhi);
    cudaGetSymbolAddress((void**)&wvl, g_wvlo);
    cudaGetSymbolAddress((void**)&woh, g_wohi);
    cudaGetSymbolAddress((void**)&wol, g_wolo);
    cudaGetSymbolAddress((void**)&w1h, g_w1hi);
    cudaGetSymbolAddress((void**)&w1l, g_w1lo);
    cudaGetSymbolAddress((void**)&w2h, g_w2hi);
    cudaGetSymbolAddress((void**)&w2l, g_w2lo);

    cudaFuncSetAttribute(attn_kernel,
                         cudaFuncAttributeMaxDynamicSharedMemorySize,
                         ATTN_SMEM_BYTES);
    cudaFuncSetAttribute(gemm_mma,
                         cudaFuncAttributeMaxDynamicSharedMemorySize,
                         GM_SMEM_BYTES);

    dim3 tb(32, 8);

    // weight transpose + split
    tsplit_kernel<<<dim3(DMODEL / 32, DMODEL / 32), tb>>>(Wq, wqh, wql, DMODEL, DMODEL);
    tsplit_kernel<<<dim3(DMODEL / 32, DMODEL / 32), tb>>>(Wk, wkh, wkl, DMODEL, DMODEL);
    tsplit_kernel<<<dim3(DMODEL / 32, DMODEL / 32), tb>>>(Wv, wvh, wvl, DMODEL, DMODEL);
    tsplit_kernel<<<dim3(DMODEL / 32, DMODEL / 32), tb>>>(Wo, woh, wol, DMODEL, DMODEL);
    tsplit_kernel<<<dim3(DFF / 32, DMODEL / 32), tb>>>(W1, w1h, w1l, DMODEL, DFF);
    tsplit_kernel<<<dim3(DMODEL / 32, DFF / 32), tb>>>(W2, w2h, w2l, DFF, DMODEL);

    // split x
    {
        int n4 = MTOK * DMODEL / 4;
        split_kernel<<<(n4 + 255) / 256, 256>>>(x, xhi, xlo, n4);
    }

    // QKV projections (tensor cores via mma.sync)
    {
        dim3 grid(DMODEL / 64, MTOK / 128);
        gemm_mma<<<grid, 256, GM_SMEM_BYTES>>>(xhi, xlo, wqh, wql, bq, q, MTOK, DMODEL, DMODEL, 0);
        gemm_mma<<<grid, 256, GM_SMEM_BYTES>>>(xhi, xlo, wkh, wkl, bk, k, MTOK, DMODEL, DMODEL, 0);
        gemm_mma<<<grid, 256, GM_SMEM_BYTES>>>(xhi, xlo, wvh, wvl, bv, v, MTOK, DMODEL, DMODEL, 0);
    }

    // attention
    {
        dim3 grid(SEQ / 64, NHEADS, BATCH);
        attn_kernel<<<grid, 256, ATTN_SMEM_BYTES>>>(q, k, v, mask, ctx);
    }

    // output projection + residual LN
    {
        int n4 = MTOK * DMODEL / 4;
        split_kernel<<<(n4 + 255) / 256, 256>>>(ctx, chi, clo, n4);
        dim3 grid(DMODEL / 64, MTOK / 128);
        gemm_mma<<<grid, 256, GM_SMEM_BYTES>>>(chi, clo, woh, wol, bo, t0, MTOK, DMODEL, DMODEL, 0);
        ln_residual_kernel<<<MTOK, 256>>>(t0, x, ln1g, ln1b, aln);
    }

    // FFN
    {
        int n4 = MTOK * DMODEL / 4;
        split_kernel<<<(n4 + 255) / 256, 256>>>(aln, ahi, alo, n4);
        dim3 grid1(DFF / 64, MTOK / 128);
        gemm_mma<<<grid1, 256, GM_SMEM_BYTES>>>(ahi, alo, w1h, w1l, b1, ff, MTOK, DFF, DMODEL, 1);

        int m4 = MTOK * DFF / 4;
        split_kernel<<<(m4 + 255) / 256, 256>>>(ff, fhi, flo, m4);
        dim3 grid2(DMODEL / 64, MTOK / 128);
        gemm_mma<<<grid2, 256, GM_SMEM_BYTES>>>(fhi, flo, w2h, w2l, b2, t0, MTOK, DMODEL, DFF, 0);
        ln_residual_kernel<<<MTOK, 256>>>(t0, aln, ln2g, ln2b, out);
    }
}

// round 4
// speedup vs baseline: 2.0637x; 1.1592x over previous
#include <cuda_runtime.h>
#include <cuda_bf16.h>
#include <math.h>
#include <stdint.h>

// ---------------------------------------------------------------------------
// Problem dims (fixed)
// ---------------------------------------------------------------------------
#define BATCH   32
#define SEQ     512
#define DMODEL  512
#define NHEADS  8
#define HDIM    64
#define DFF     2048
#define MTOK    (BATCH * SEQ)          // 16384 rows
#define LN_EPS  1e-12f

// ---------------------------------------------------------------------------
// Scratch (device globals; no runtime allocation allowed)
// ---------------------------------------------------------------------------
__device__ float g_q[MTOK * DMODEL];
__device__ float g_k[MTOK * DMODEL];
__device__ float g_v[MTOK * DMODEL];
__device__ float g_ctx[MTOK * DMODEL];
__device__ float g_t0[MTOK * DMODEL];
__device__ float g_attnln[MTOK * DMODEL];
__device__ float g_ff[MTOK * DFF];

// bf16 hi/lo split activations
__device__ __nv_bfloat16 g_xhi[MTOK * DMODEL];
__device__ __nv_bfloat16 g_xlo[MTOK * DMODEL];
__device__ __nv_bfloat16 g_chi[MTOK * DMODEL];
__device__ __nv_bfloat16 g_clo[MTOK * DMODEL];
__device__ __nv_bfloat16 g_ahi[MTOK * DMODEL];
__device__ __nv_bfloat16 g_alo[MTOK * DMODEL];
__device__ __nv_bfloat16 g_fhi[MTOK * DFF];
__device__ __nv_bfloat16 g_flo[MTOK * DFF];

// bf16 hi/lo split transposed weights [N][K]
__device__ __nv_bfloat16 g_wqhi[DMODEL * DMODEL];
__device__ __nv_bfloat16 g_wqlo[DMODEL * DMODEL];
__device__ __nv_bfloat16 g_wkhi[DMODEL * DMODEL];
__device__ __nv_bfloat16 g_wklo[DMODEL * DMODEL];
__device__ __nv_bfloat16 g_wvhi[DMODEL * DMODEL];
__device__ __nv_bfloat16 g_wvlo[DMODEL * DMODEL];
__device__ __nv_bfloat16 g_wohi[DMODEL * DMODEL];
__device__ __nv_bfloat16 g_wolo[DMODEL * DMODEL];
__device__ __nv_bfloat16 g_w1hi[DFF * DMODEL];
__device__ __nv_bfloat16 g_w1lo[DFF * DMODEL];
__device__ __nv_bfloat16 g_w2hi[DMODEL * DFF];
__device__ __nv_bfloat16 g_w2lo[DMODEL * DFF];

// ---------------------------------------------------------------------------
// mma.sync helper (bf16 -> f32, m16n8k16)
// ---------------------------------------------------------------------------
__device__ __forceinline__ void mma16816(float* c, const uint32_t* a, const uint32_t* b)
{
    asm volatile(
        "mma.sync.aligned.m16n8k16.row.col.f32.bf16.bf16.f32 "
        "{%0,%1,%2,%3}, {%4,%5,%6,%7}, {%8,%9}, {%0,%1,%2,%3};"
        : "+f"(c[0]), "+f"(c[1]), "+f"(c[2]), "+f"(c[3])
        : "r"(a[0]), "r"(a[1]), "r"(a[2]), "r"(a[3]), "r"(b[0]), "r"(b[1]));
}

// ---------------------------------------------------------------------------
// FMA-only exp (avoids MUFU.EX2 throughput floor); ~2e-6 rel on x <= 0
// ---------------------------------------------------------------------------
__device__ __forceinline__ float fast_exp(float x) {
    float y = fmaxf(x * 1.4426950408889634f, -120.0f);
    float n = rintf(y);
    float f = y - n;
    float p = 1.3333558e-3f;
    p = fmaf(p, f, 9.6181291e-3f);
    p = fmaf(p, f, 5.5504109e-2f);
    p = fmaf(p, f, 2.4022651e-1f);
    p = fmaf(p, f, 6.9314718e-1f);
    p = fmaf(p, f, 1.0f);
    return p * __int_as_float(((int)n + 127) << 23);
}

// ---------------------------------------------------------------------------
// fp32 -> bf16 hi/lo split
// ---------------------------------------------------------------------------
__device__ __forceinline__ void split1(float v, unsigned short& h, unsigned short& l) {
    __nv_bfloat16 hb = __float2bfloat16_rn(v);
    float r = v - __bfloat162float(hb);
    __nv_bfloat16 lb = __float2bfloat16_rn(r);
    h = __bfloat16_as_ushort(hb);
    l = __bfloat16_as_ushort(lb);
}

__global__ void split_kernel(const float* __restrict__ X,
                             __nv_bfloat16* __restrict__ hi,
                             __nv_bfloat16* __restrict__ lo, int n4)
{
    int i = blockIdx.x * blockDim.x + threadIdx.x;
    if (i >= n4) return;
    float4 x = ((const float4*)X)[i];
    unsigned short h0, h1, h2, h3, l0, l1, l2, l3;
    split1(x.x, h0, l0); split1(x.y, h1, l1);
    split1(x.z, h2, l2); split1(x.w, h3, l3);
    uint2 hv, lv;
    hv.x = (uint32_t)h0 | ((uint32_t)h1 << 16);
    hv.y = (uint32_t)h2 | ((uint32_t)h3 << 16);
    lv.x = (uint32_t)l0 | ((uint32_t)l1 << 16);
    lv.y = (uint32_t)l2 | ((uint32_t)l3 << 16);
    ((uint2*)hi)[i] = hv;
    ((uint2*)lo)[i] = lv;
}

// Transpose + split: W[K][N] fp32 -> hi/lo [N][K] bf16
__global__ void tsplit_kernel(const float* __restrict__ W,
                              __nv_bfloat16* __restrict__ hi,
                              __nv_bfloat16* __restrict__ lo,
                              int K, int N)
{
    __shared__ float tile[32][33];
    const int n0 = blockIdx.x * 32, k0 = blockIdx.y * 32;
    const int tx = threadIdx.x, ty = threadIdx.y;   // 32 x 8
#pragma unroll
    for (int i = 0; i < 32; i += 8)
        tile[ty + i][tx] = W[(size_t)(k0 + ty + i) * N + n0 + tx];
    __syncthreads();
#pragma unroll
    for (int i = 0; i < 32; i += 8) {
        float v = tile[tx][ty + i];
        unsigned short h, l;
        split1(v, h, l);
        size_t o = (size_t)(n0 + ty + i) * K + k0 + tx;
        hi[o] = __ushort_as_bfloat16(h);
        lo[o] = __ushort_as_bfloat16(l);
    }
}

// ---------------------------------------------------------------------------
// Tensor-core split-GEMM (unchanged from round 3 — passing)
// ---------------------------------------------------------------------------
#define SA 72
#define GM_A_ELEMS (128 * SA)
#define GM_B_ELEMS (64 * SA)
#define GM_SMEM_ELEMS (2 * GM_A_ELEMS + 2 * GM_B_ELEMS)
#define GM_SMEM_BYTES (GM_SMEM_ELEMS * 2)

__global__ __launch_bounds__(256)
void gemm_mma(const __nv_bfloat16* __restrict__ Ahi,
              const __nv_bfloat16* __restrict__ Alo,
              const __nv_bfloat16* __restrict__ Bhi,
              const __nv_bfloat16* __restrict__ Blo,
              const float* __restrict__ bias,
              float* __restrict__ C,
              int M, int N, int K, int do_gelu)
{
    extern __shared__ __nv_bfloat16 smb[];
    __nv_bfloat16* As_hi = smb;
    __nv_bfloat16* As_lo = smb + GM_A_ELEMS;
    __nv_bfloat16* Bs_hi = smb + 2 * GM_A_ELEMS;
    __nv_bfloat16* Bs_lo = smb + 2 * GM_A_ELEMS + GM_B_ELEMS;

    const int tid = threadIdx.x;
    const int wid = tid >> 5;
    const int lid = tid & 31;
    const int gID = lid >> 2;
    const int t4  = lid & 3;

    const int row0 = blockIdx.y * 128;
    const int col0 = blockIdx.x * 64;
    const int m_off = (wid & 3) * 32;
    const int n_off = (wid >> 2) * 32;

    float acc[2][4][4];
#pragma unroll
    for (int mi = 0; mi < 2; mi++)
#pragma unroll
        for (int ni = 0; ni < 4; ni++)
#pragma unroll
            for (int j = 0; j < 4; j++) acc[mi][ni][j] = 0.f;

    const int nT = K >> 6;
    for (int t = 0; t < nT; t++) {
        const int kb = t << 6;
#pragma unroll
        for (int i = 0; i < 4; i++) {
            int e = tid + i * 256;
            int r = e >> 3, g = e & 7;
            int ds = r * SA + g * 8;
            size_t src = (size_t)(row0 + r) * K + kb + g * 8;
            *(uint4*)&As_hi[ds] = *(const uint4*)&Ahi[src];
            *(uint4*)&As_lo[ds] = *(const uint4*)&Alo[src];
        }
#pragma unroll
        for (int i = 0; i < 2; i++) {
            int e = tid + i * 256;
            int r = e >> 3, g = e & 7;
            int ds = r * SA + g * 8;
            size_t src = (size_t)(col0 + r) * K + kb + g * 8;
            *(uint4*)&Bs_hi[ds] = *(const uint4*)&Bhi[src];
            *(uint4*)&Bs_lo[ds] = *(const uint4*)&Blo[src];
        }
        __syncthreads();

#pragma unroll
        for (int kk = 0; kk < 64; kk += 16) {
            uint32_t ahi[2][4], alo[2][4], bhi[4][2], blo[4][2];
#pragma unroll
            for (int mi = 0; mi < 2; mi++) {
                int r = m_off + mi * 16 + gID;
                int base0 = r * SA + kk + t4 * 2;
                int base1 = (r + 8) * SA + kk + t4 * 2;
                ahi[mi][0] = *(const uint32_t*)&As_hi[base0];
                ahi[mi][1] = *(const uint32_t*)&As_hi[base1];
                ahi[mi][2] = *(const uint32_t*)&As_hi[base0 + 8];
                ahi[mi][3] = *(const uint32_t*)&As_hi[base1 + 8];
                alo[mi][0] = *(const uint32_t*)&As_lo[base0];
                alo[mi][1] = *(const uint32_t*)&As_lo[base1];
                alo[mi][2] = *(const uint32_t*)&As_lo[base0 + 8];
                alo[mi][3] = *(const uint32_t*)&As_lo[base1 + 8];
            }
#pragma unroll
            for (int ni = 0; ni < 4; ni++) {
                int n = n_off + ni * 8 + gID;
                int base = n * SA + kk + t4 * 2;
                bhi[ni][0] = *(const uint32_t*)&Bs_hi[base];
                bhi[ni][1] = *(const uint32_t*)&Bs_hi[base + 8];
                blo[ni][0] = *(const uint32_t*)&Bs_lo[base];
                blo[ni][1] = *(const uint32_t*)&Bs_lo[base + 8];
            }
#pragma unroll
            for (int mi = 0; mi < 2; mi++)
#pragma unroll
                for (int ni = 0; ni < 4; ni++) {
                    mma16816(acc[mi][ni], ahi[mi], bhi[ni]);
                    mma16816(acc[mi][ni], alo[mi], bhi[ni]);
                    mma16816(acc[mi][ni], ahi[mi], blo[ni]);
                }
        }
        __syncthreads();
    }

#pragma unroll
    for (int mi = 0; mi < 2; mi++) {
#pragma unroll
        for (int ni = 0; ni < 4; ni++) {
            int col = col0 + n_off + ni * 8 + t4 * 2;
            float b0 = bias[col], b1 = bias[col + 1];
#pragma unroll
            for (int half = 0; half < 2; half++) {
                int row = row0 + m_off + mi * 16 + gID + half * 8;
                float v0 = acc[mi][ni][half * 2 + 0] + b0;
                float v1 = acc[mi][ni][half * 2 + 1] + b1;
                if (do_gelu) {
                    v0 = 0.5f * v0 * (1.0f + erff(v0 * 0.70710678118654752f));
                    v1 = 0.5f * v1 * (1.0f + erff(v1 * 0.70710678118654752f));
                }
                float2 o; o.x = v0; o.y = v1;
                *(float2*)(C + (size_t)row * N + col) = o;
            }
        }
    }
}

// ---------------------------------------------------------------------------
// Tensor-core attention: CTA = (q-tile 64, head, batch), 256 threads.
// Scores via 3-term bf16 split HMMA; fp32 score block in smem; softmax with
// FMA exp; P normalized+split during conversion; P@V via 3-term HMMA with
// V transposed+split on the fly.
// ---------------------------------------------------------------------------
#define AT_SA   72
#define AT_QHI  0
#define AT_QLO  9216
#define AT_KHI  18432
#define AT_KLO  27648
#define AT_PHI  36864
#define AT_PLO  46080
#define AT_SS   55296
#define AT_INV  (AT_SS + 64 * 512 * 4)       // 186368
#define AT_SMEM (AT_INV + 256)               // 186624

__global__ __launch_bounds__(256)
void attn_mma(const float* __restrict__ Qg,
              const float* __restrict__ Kg,
              const float* __restrict__ Vg,
              const float* __restrict__ mask,
              float* __restrict__ Og)
{
    extern __shared__ char smc[];
    __nv_bfloat16* Qhi = (__nv_bfloat16*)(smc + AT_QHI);
    __nv_bfloat16* Qlo = (__nv_bfloat16*)(smc + AT_QLO);
    __nv_bfloat16* Khi = (__nv_bfloat16*)(smc + AT_KHI);   // also Vt hi
    __nv_bfloat16* Klo = (__nv_bfloat16*)(smc + AT_KLO);   // also Vt lo
    __nv_bfloat16* Phi = (__nv_bfloat16*)(smc + AT_PHI);
    __nv_bfloat16* Plo = (__nv_bfloat16*)(smc + AT_PLO);
    float* Ss   = (float*)(smc + AT_SS);
    float* invs = (float*)(smc + AT_INV);

    const int tid = threadIdx.x;
    const int wid = tid >> 5, lid = tid & 31;
    const int gID = lid >> 2, t4 = lid & 3;
    const int wm = wid & 3, wn = wid >> 2;
    const int q0 = blockIdx.x * 64;
    const int h = blockIdx.y, b = blockIdx.z;
    const size_t hb = ((size_t)b * SEQ) * DMODEL + (size_t)h * HDIM;
    const float* mbase = mask + (size_t)b * SEQ * SEQ;

    // ---- load Q tile 64x64, split hi/lo ----
#pragma unroll
    for (int i = 0; i < 4; i++) {
        int e = tid + i * 256;
        int r = e >> 4, c4 = e & 15;
        float4 v = *(const float4*)(Qg + hb + (size_t)(q0 + r) * DMODEL + c4 * 4);
        unsigned short h0, h1, h2, h3, l0, l1, l2, l3;
        split1(v.x, h0, l0); split1(v.y, h1, l1);
        split1(v.z, h2, l2); split1(v.w, h3, l3);
        uint2 hv, lv;
        hv.x = (uint32_t)h0 | ((uint32_t)h1 << 16);
        hv.y = (uint32_t)h2 | ((uint32_t)h3 << 16);
        lv.x = (uint32_t)l0 | ((uint32_t)l1 << 16);
        lv.y = (uint32_t)l2 | ((uint32_t)l3 << 16);
        *(uint2*)(Qhi + r * AT_SA + c4 * 4) = hv;
        *(uint2*)(Qlo + r * AT_SA + c4 * 4) = lv;
    }

    float pv[4][4];
#pragma unroll
    for (int ni = 0; ni < 4; ni++)
#pragma unroll
        for (int j = 0; j < 4; j++) pv[ni][j] = 0.f;

    // ---- phase 1: scores ----
    for (int kc = 0; kc < 8; kc++) {
        const int k0 = kc * 64;
        __syncthreads();
#pragma unroll
        for (int i = 0; i < 4; i++) {
            int e = tid + i * 256;
            int r = e >> 4, c4 = e & 15;
            float4 v = *(const float4*)(Kg + hb + (size_t)(k0 + r) * DMODEL + c4 * 4);
            unsigned short h0, h1, h2, h3, l0, l1, l2, l3;
            split1(v.x, h0, l0); split1(v.y, h1, l1);
            split1(v.z, h2, l2); split1(v.w, h3, l3);
            uint2 hv, lv;
            hv.x = (uint32_t)h0 | ((uint32_t)h1 << 16);
            hv.y = (uint32_t)h2 | ((uint32_t)h3 << 16);
            lv.x = (uint32_t)l0 | ((uint32_t)l1 << 16);
            lv.y = (uint32_t)l2 | ((uint32_t)l3 << 16);
            *(uint2*)(Khi + r * AT_SA + c4 * 4) = hv;
            *(uint2*)(Klo + r * AT_SA + c4 * 4) = lv;
        }
        __syncthreads();

        float s[4][4];
#pragma unroll
        for (int ni = 0; ni < 4; ni++)
#pragma unroll
            for (int j = 0; j < 4; j++) s[ni][j] = 0.f;

#pragma unroll
        for (int kk = 0; kk < 64; kk += 16) {
            uint32_t ah[4], al[4];
            int rb0 = (wm * 16 + gID) * AT_SA + kk + t4 * 2;
            int rb1 = rb0 + 8 * AT_SA;
            ah[0] = *(const uint32_t*)&Qhi[rb0];
            ah[1] = *(const uint32_t*)&Qhi[rb1];
            ah[2] = *(const uint32_t*)&Qhi[rb0 + 8];
            ah[3] = *(const uint32_t*)&Qhi[rb1 + 8];
            al[0] = *(const uint32_t*)&Qlo[rb0];
            al[1] = *(const uint32_t*)&Qlo[rb1];
            al[2] = *(const uint32_t*)&Qlo[rb0 + 8];
            al[3] = *(const uint32_t*)&Qlo[rb1 + 8];
#pragma unroll
            for (int ni = 0; ni < 4; ni++) {
                int nb = (wn * 32 + ni * 8 + gID) * AT_SA + kk + t4 * 2;
                uint32_t bh[2], bl[2];
                bh[0] = *(const uint32_t*)&Khi[nb];
                bh[1] = *(const uint32_t*)&Khi[nb + 8];
                bl[0] = *(const uint32_t*)&Klo[nb];
                bl[1] = *(const uint32_t*)&Klo[nb + 8];
                mma16816(s[ni], ah, bh);
                mma16816(s[ni], al, bh);
                mma16816(s[ni], ah, bl);
            }
        }
        // epilogue: scale + mask -> Ss
#pragma unroll
        for (int ni = 0; ni < 4; ni++) {
            int col = k0 + wn * 32 + ni * 8 + t4 * 2;
#pragma unroll
            for (int hf = 0; hf < 2; hf++) {
                int row = wm * 16 + gID + hf * 8;
                float2 m2 = *(const float2*)(mbase + (size_t)(q0 + row) * SEQ + col);
                float2 o;
                o.x = s[ni][hf * 2 + 0] * 0.125f + m2.x;
                o.y = s[ni][hf * 2 + 1] * 0.125f + m2.y;
                *(float2*)(Ss + row * 512 + col) = o;
            }
        }
    }
    __syncthreads();

    // ---- phase 2: softmax (exp stored unnormalized; invsum saved) ----
    {
#pragma unroll
        for (int rr = 0; rr < 8; rr++) {
            int r = wid * 8 + rr;
            float* row = Ss + r * 512;
            float4 v[4];
#pragma unroll
            for (int it = 0; it < 4; it++)
                v[it] = *(float4*)(row + it * 128 + lid * 4);
            float m = -1e30f;
#pragma unroll
            for (int it = 0; it < 4; it++) {
                m = fmaxf(m, fmaxf(fmaxf(v[it].x, v[it].y), fmaxf(v[it].z, v[it].w)));
            }
#pragma unroll
            for (int off = 16; off; off >>= 1)
                m = fmaxf(m, __shfl_xor_sync(0xffffffffu, m, off));
            float sum = 0.f;
#pragma unroll
            for (int it = 0; it < 4; it++) {
                v[it].x = fast_exp(v[it].x - m);
                v[it].y = fast_exp(v[it].y - m);
                v[it].z = fast_exp(v[it].z - m);
                v[it].w = fast_exp(v[it].w - m);
                sum += v[it].x + v[it].y + v[it].z + v[it].w;
                *(float4*)(row + it * 128 + lid * 4) = v[it];
            }
#pragma unroll
            for (int off = 16; off; off >>= 1)
                sum += __shfl_xor_sync(0xffffffffu, sum, off);
            if (lid == 0) invs[r] = 1.0f / sum;
        }
    }

    // ---- phase 3: P @ V ----
    for (int kc = 0; kc < 8; kc++) {
        const int k0 = kc * 64;
        __syncthreads();   // prior mma reads done (or softmax done on kc==0)

        // convert P chunk (normalize + split) -> Phi/Plo
        {
            int r = tid >> 2, c0 = (tid & 3) * 16;
            float is = invs[r];
#pragma unroll
            for (int j2 = 0; j2 < 2; j2++) {
                const float* src = Ss + r * 512 + k0 + c0 + j2 * 8;
                float4 a = *(const float4*)(src);
                float4 bq = *(const float4*)(src + 4);
                float vals[8] = {a.x * is, a.y * is, a.z * is, a.w * is,
                                 bq.x * is, bq.y * is, bq.z * is, bq.w * is};
                unsigned short hh[8], ll[8];
#pragma unroll
                for (int j = 0; j < 8; j++) split1(vals[j], hh[j], ll[j]);
                uint4 hv, lv;
                hv.x = (uint32_t)hh[0] | ((uint32_t)hh[1] << 16);
                hv.y = (uint32_t)hh[2] | ((uint32_t)hh[3] << 16);
                hv.z = (uint32_t)hh[4] | ((uint32_t)hh[5] << 16);
                hv.w = (uint32_t)hh[6] | ((uint32_t)hh[7] << 16);
                lv.x = (uint32_t)ll[0] | ((uint32_t)ll[1] << 16);
                lv.y = (uint32_t)ll[2] | ((uint32_t)ll[3] << 16);
                lv.z = (uint32_t)ll[4] | ((uint32_t)ll[5] << 16);
                lv.w = (uint32_t)ll[6] | ((uint32_t)ll[7] << 16);
                *(uint4*)(Phi + r * AT_SA + c0 + j2 * 8) = hv;
                *(uint4*)(Plo + r * AT_SA + c0 + j2 * 8) = lv;
            }
        }

        // load V chunk transposed+split -> Khi/Klo (reused as Vt)
#pragma unroll
        for (int i = 0; i < 4; i++) {
            int e = tid + i * 256;
            int r = e >> 4, c4 = e & 15;
            float4 v = *(const float4*)(Vg + hb + (size_t)(k0 + r) * DMODEL + c4 * 4);
            unsigned short hh, ll;
            split1(v.x, hh, ll);
            Khi[(c4 * 4 + 0) * AT_SA + r] = __ushort_as_bfloat16(hh);
            Klo[(c4 * 4 + 0) * AT_SA + r] = __ushort_as_bfloat16(ll);
            split1(v.y, hh, ll);
            Khi[(c4 * 4 + 1) * AT_SA + r] = __ushort_as_bfloat16(hh);
            Klo[(c4 * 4 + 1) * AT_SA + r] = __ushort_as_bfloat16(ll);
            split1(v.z, hh, ll);
            Khi[(c4 * 4 + 2) * AT_SA + r] = __ushort_as_bfloat16(hh);
            Klo[(c4 * 4 + 2) * AT_SA + r] = __ushort_as_bfloat16(ll);
            split1(v.w, hh, ll);
            Khi[(c4 * 4 + 3) * AT_SA + r] = __ushort_as_bfloat16(hh);
            Klo[(c4 * 4 + 3) * AT_SA + r] = __ushort_as_bfloat16(ll);
        }
        __syncthreads();

#pragma unroll
        for (int kk = 0; kk < 64; kk += 16) {
            uint32_t ah[4], al[4];
            int rb0 = (wm * 16 + gID) * AT_SA + kk + t4 * 2;
            int rb1 = rb0 + 8 * AT_SA;
            ah[0] = *(const uint32_t*)&Phi[rb0];
            ah[1] = *(const uint32_t*)&Phi[rb1];
            ah[2] = *(const uint32_t*)&Phi[rb0 + 8];
            ah[3] = *(const uint32_t*)&Phi[rb1 + 8];
            al[0] = *(const uint32_t*)&Plo[rb0];
            al[1] = *(const uint32_t*)&Plo[rb1];
            al[2] = *(const uint32_t*)&Plo[rb0 + 8];
            al[3] = *(const uint32_t*)&Plo[rb1 + 8];
#pragma unroll
            for (int ni = 0; ni < 4; ni++) {
                int nb = (wn * 32 + ni * 8 + gID) * AT_SA + kk + t4 * 2;
                uint32_t bh[2], bl[2];
                bh[0] = *(const uint32_t*)&Khi[nb];
                bh[1] = *(const uint32_t*)&Khi[nb + 8];
                bl[0] = *(const uint32_t*)&Klo[nb];
                bl[1] = *(const uint32_t*)&Klo[nb + 8];
                mma16816(pv[ni], ah, bh);
                mma16816(pv[ni], al, bh);
                mma16816(pv[ni], ah, bl);
            }
        }
    }

    // ---- write ctx ----
#pragma unroll
    for (int ni = 0; ni < 4; ni++) {
        int d = wn * 32 + ni * 8 + t4 * 2;
#pragma unroll
        for (int hf = 0; hf < 2; hf++) {
            int row = wm * 16 + gID + hf * 8;
            float2 o;
            o.x = pv[ni][hf * 2 + 0];
            o.y = pv[ni][hf * 2 + 1];
            *(float2*)(Og + hb + (size_t)(q0 + row) * DMODEL + d) = o;
        }
    }
}

// ---------------------------------------------------------------------------
// LayerNorm with residual (unchanged)
// ---------------------------------------------------------------------------
__global__ void ln_residual_kernel(const float* __restrict__ y,
                                   const float* __restrict__ res,
                                   const float* __restrict__ g,
                                   const float* __restrict__ bta,
                                   float* __restrict__ out)
{
    __shared__ float red[256];
    const int r = blockIdx.x;
    const int tid = threadIdx.x;
    const size_t off = (size_t)r * DMODEL;

    float v0 = y[off + tid]        + res[off + tid];
    float v1 = y[off + tid + 256]  + res[off + tid + 256];

    red[tid] = v0 + v1;
    __syncthreads();
#pragma unroll
    for (int s = 128; s; s >>= 1) {
        if (tid < s) red[tid] += red[tid + s];
        __syncthreads();
    }
    float mean = red[0] * (1.0f / 512.0f);
    __syncthreads();

    float d0 = v0 - mean, d1 = v1 - mean;
    red[tid] = d0 * d0 + d1 * d1;
    __syncthreads();
#pragma unroll
    for (int s = 128; s; s >>= 1) {
        if (tid < s) red[tid] += red[tid + s];
        __syncthreads();
    }
    float inv = rsqrtf(red[0] * (1.0f / 512.0f) + LN_EPS);

    out[off + tid]       = d0 * inv * g[tid]       + bta[tid];
    out[off + tid + 256] = d1 * inv * g[tid + 256] + bta[tid + 256];
}

// ---------------------------------------------------------------------------
// launch
// ---------------------------------------------------------------------------
extern "C" void kernel_launch(void* const* d_in, const int* in_sizes, int n_in,
                              void* d_out, int out_size)
{
    const float* x     = (const float*)d_in[0];
    const float* mask  = (const float*)d_in[1];
    const float* Wq    = (const float*)d_in[2];
    const float* bq    = (const float*)d_in[3];
    const float* Wk    = (const float*)d_in[4];
    const float* bk    = (const float*)d_in[5];
    const float* Wv    = (const float*)d_in[6];
    const float* bv    = (const float*)d_in[7];
    const float* Wo    = (const float*)d_in[8];
    const float* bo    = (const float*)d_in[9];
    const float* ln1g  = (const float*)d_in[10];
    const float* ln1b  = (const float*)d_in[11];
    const float* W1    = (const float*)d_in[12];
    const float* b1    = (const float*)d_in[13];
    const float* W2    = (const float*)d_in[14];
    const float* b2    = (const float*)d_in[15];
    const float* ln2g  = (const float*)d_in[16];
    const float* ln2b  = (const float*)d_in[17];
    float* out = (float*)d_out;

    float *q, *k, *v, *ctx, *t0, *aln, *ff;
    cudaGetSymbolAddress((void**)&q,   g_q);
    cudaGetSymbolAddress((void**)&k,   g_k);
    cudaGetSymbolAddress((void**)&v,   g_v);
    cudaGetSymbolAddress((void**)&ctx, g_ctx);
    cudaGetSymbolAddress((void**)&t0,  g_t0);
    cudaGetSymbolAddress((void**)&aln, g_attnln);
    cudaGetSymbolAddress((void**)&ff,  g_ff);

    __nv_bfloat16 *xhi, *xlo, *chi, *clo, *ahi, *alo, *fhi, *flo;
    cudaGetSymbolAddress((void**)&xhi, g_xhi);
    cudaGetSymbolAddress((void**)&xlo, g_xlo);
    cudaGetSymbolAddress((void**)&chi, g_chi);
    cudaGetSymbolAddress((void**)&clo, g_clo);
    cudaGetSymbolAddress((void**)&ahi, g_ahi);
    cudaGetSymbolAddress((void**)&alo, g_alo);
    cudaGetSymbolAddress((void**)&fhi, g_fhi);
    cudaGetSymbolAddress((void**)&flo, g_flo);

    __nv_bfloat16 *wqh, *wql, *wkh, *wkl, *wvh, *wvl, *woh, *wol, *w1h, *w1l, *w2h, *w2l;
    cudaGetSymbolAddress((void**)&wqh, g_wqhi);
    cudaGetSymbolAddress((void**)&wql, g_wqlo);
    cudaGetSymbolAddress((void**)&wkh, g_wkhi);
    cudaGetSymbolAddress((void**)&wkl, g_wklo);
    cudaGetSymbolAddress((void**)&wvh, g_wvhi);
    cudaGetSymbolAddress((void**)&wvl, g_wvlo);
    cudaGetSymbolAddress((void**)&woh, g_wohi);
    cudaGetSymbolAddress((void**)&wol, g_wolo);
    cudaGetSymbolAddress((void**)&w1h, g_w1hi);
    cudaGetSymbolAddress((void**)&w1l, g_w1lo);
    cudaGetSymbolAddress((void**)&w2h, g_w2hi);
    cudaGetSymbolAddress((void**)&w2l, g_w2lo);

    cudaFuncSetAttribute(attn_mma,
                         cudaFuncAttributeMaxDynamicSharedMemorySize,
                         AT_SMEM);
    cudaFuncSetAttribute(gemm_mma,
                         cudaFuncAttributeMaxDynamicSharedMemorySize,
                         GM_SMEM_BYTES);

    dim3 tb(32, 8);

    // weight transpose + split
    tsplit_kernel<<<dim3(DMODEL / 32, DMODEL / 32), tb>>>(Wq, wqh, wql, DMODEL, DMODEL);
    tsplit_kernel<<<dim3(DMODEL / 32, DMODEL / 32), tb>>>(Wk, wkh, wkl, DMODEL, DMODEL);
    tsplit_kernel<<<dim3(DMODEL / 32, DMODEL / 32), tb>>>(Wv, wvh, wvl, DMODEL, DMODEL);
    tsplit_kernel<<<dim3(DMODEL / 32, DMODEL / 32), tb>>>(Wo, woh, wol, DMODEL, DMODEL);
    tsplit_kernel<<<dim3(DFF / 32, DMODEL / 32), tb>>>(W1, w1h, w1l, DMODEL, DFF);
    tsplit_kernel<<<dim3(DMODEL / 32, DFF / 32), tb>>>(W2, w2h, w2l, DFF, DMODEL);

    // split x
    {
        int n4 = MTOK * DMODEL / 4;
        split_kernel<<<(n4 + 255) / 256, 256>>>(x, xhi, xlo, n4);
    }

    // QKV projections
    {
        dim3 grid(DMODEL / 64, MTOK / 128);
        gemm_mma<<<grid, 256, GM_SMEM_BYTES>>>(xhi, xlo, wqh, wql, bq, q, MTOK, DMODEL, DMODEL, 0);
        gemm_mma<<<grid, 256, GM_SMEM_BYTES>>>(xhi, xlo, wkh, wkl, bk, k, MTOK, DMODEL, DMODEL, 0);
        gemm_mma<<<grid, 256, GM_SMEM_BYTES>>>(xhi, xlo, wvh, wvl, bv, v, MTOK, DMODEL, DMODEL, 0);
    }

    // attention (tensor cores)
    {
        dim3 grid(SEQ / 64, NHEADS, BATCH);
        attn_mma<<<grid, 256, AT_SMEM>>>(q, k, v, mask, ctx);
    }

    // output projection + residual LN
    {
        int n4 = MTOK * DMODEL / 4;
        split_kernel<<<(n4 + 255) / 256, 256>>>(ctx, chi, clo, n4);
        dim3 grid(DMODEL / 64, MTOK / 128);
        gemm_mma<<<grid, 256, GM_SMEM_BYTES>>>(chi, clo, woh, wol, bo, t0, MTOK, DMODEL, DMODEL, 0);
        ln_residual_kernel<<<MTOK, 256>>>(t0, x, ln1g, ln1b, aln);
    }

    // FFN
    {
        int n4 = MTOK * DMODEL / 4;
        split_kernel<<<(n4 + 255) / 256, 256>>>(aln, ahi, alo, n4);
        dim3 grid1(DFF / 64, MTOK / 128);
        gemm_mma<<<grid1, 256, GM_SMEM_BYTES>>>(ahi, alo, w1h, w1l, b1, ff, MTOK, DFF, DMODEL, 1);

        int m4 = MTOK * DFF / 4;
        split_kernel<<<(m4 + 255) / 256, 256>>>(ff, fhi, flo, m4);
        dim3 grid2(DMODEL / 64, MTOK / 128);
        gemm_mma<<<grid2, 256, GM_SMEM_BYTES>>>(fhi, flo, w2h, w2l, b2, t0, MTOK, DMODEL, DFF, 0);
        ln_residual_kernel<<<MTOK, 256>>>(t0, aln, ln2g, ln2b, out);
    }
}